// round 9
// baseline (speedup 1.0000x reference)
#include <cuda_runtime.h>
#include <cstdint>

#define N_NODES 100000
#define N_EDGES 800000
#define N_GRAPHS 512
#define DH 128
#define EPS_BN 1e-5f
#define NCHUNK 196   // ceil(100000/512)

// ---------------- scratch (device globals; no allocations allowed) ----------------
__device__ float g_bufH[(size_t)N_NODES * DH];   // current activations
__device__ float g_bufT[(size_t)N_NODES * DH];   // post-GEMM temp
__device__ int   g_deg[N_NODES];
__device__ int   g_off[N_NODES + 1];
__device__ int   g_cur[N_NODES];
__device__ int   g_csr_src[N_EDGES];
__device__ float g_csr_w[N_EDGES];
__device__ float g_dinv[N_NODES];
__device__ int   g_csum[256];
__device__ int   g_cbase[256];
__device__ float g_bn[256];                      // [0:128) sum, [128:256) sumsq
__device__ float g_scale[DH];
__device__ float g_shift[DH];
__device__ float g_pool[(size_t)N_GRAPHS * DH];
__device__ float g_pcnt[N_GRAPHS];
__device__ int   g_is64;                         // 1 if index inputs are int64, 0 if int32

// ---------------- dtype detection ----------------
// If edge_index is int64 (values nonnegative, < 2^31), every odd int32 word is 0.
// If it is int32 (random values in [0, 100000)), odd words are nonzero w.p. ~1.
__global__ void k_detect(const int* __restrict__ ei32) {
    if (threadIdx.x == 0) {
        int nz = 0;
        for (int i = 0; i < 1024; i++) nz |= ei32[2 * i + 1];
        g_is64 = (nz == 0) ? 1 : 0;
    }
}

// ---------------- index fetch helpers (clamped: traps become rel_err, not 717) ----
__device__ __forceinline__ int load_idx(const void* p, long long i, int limit) {
    int v;
    if (g_is64) v = (int)((const long long*)p)[i];
    else        v = ((const int*)p)[i];
    v = v < 0 ? 0 : v;
    return v >= limit ? limit - 1 : v;
}

// ---------------- setup kernels ----------------
__global__ void k_zero_deg() {
    int i = blockIdx.x * blockDim.x + threadIdx.x;
    if (i < N_NODES) g_deg[i] = 0;
}

__global__ void k_edge_deg(const void* __restrict__ eiv) {
    int e = blockIdx.x * blockDim.x + threadIdx.x;
    if (e < N_EDGES) {
        int d = load_idx(eiv, (long long)N_EDGES + e, N_NODES);
        atomicAdd(&g_deg[d], 1);
    }
}

__global__ void k_scan_local() {
    __shared__ int sh[512];
    int i = blockIdx.x * 512 + threadIdx.x;
    int v = (i < N_NODES) ? g_deg[i] : 0;
    sh[threadIdx.x] = v;
    __syncthreads();
    for (int off = 1; off < 512; off <<= 1) {
        int t = (threadIdx.x >= off) ? sh[threadIdx.x - off] : 0;
        __syncthreads();
        sh[threadIdx.x] += t;
        __syncthreads();
    }
    if (i < N_NODES) g_off[i] = sh[threadIdx.x] - v;   // exclusive
    if (threadIdx.x == 511) g_csum[blockIdx.x] = sh[511];
}

__global__ void k_scan_chunks() {
    if (threadIdx.x == 0) {
        int run = 0;
        for (int c = 0; c < NCHUNK; c++) {
            g_cbase[c] = run;
            run += g_csum[c];
        }
        g_off[N_NODES] = run;   // == N_EDGES
    }
}

__global__ void k_scan_apply() {
    int i = blockIdx.x * 512 + threadIdx.x;
    if (i < N_NODES) {
        int off = g_off[i] + g_cbase[i >> 9];
        g_off[i] = off;
        g_cur[i] = off;
        g_dinv[i] = rsqrtf((float)g_deg[i] + 1.0f);
    }
}

__global__ void k_csr_fill(const void* __restrict__ eiv) {
    int e = blockIdx.x * blockDim.x + threadIdx.x;
    if (e < N_EDGES) {
        int s = load_idx(eiv, e, N_NODES);
        int d = load_idx(eiv, (long long)N_EDGES + e, N_NODES);
        int pos = atomicAdd(&g_cur[d], 1);
        pos = pos < 0 ? 0 : (pos >= N_EDGES ? N_EDGES - 1 : pos);
        g_csr_src[pos] = s;
        g_csr_w[pos] = g_dinv[s] * g_dinv[d];
    }
}

// ---------------- GEMM: C[M,128] = act(A) @ W[128,128] ----------------
// act (layers 1,2): y = relu(x * g_scale[c] + g_shift[c])  (fused BN apply + relu)
// BM=128, BN=128, BK=32, 256 threads, each thread an 8x8 micro-tile (plain fmaf).
template <bool ACT, bool FIRST>
__global__ __launch_bounds__(256)
void k_gemm(const float* __restrict__ Ax, const float* __restrict__ W) {
    __shared__ __align__(16) float As[32][132];   // [k][row]
    __shared__ __align__(16) float Bs[32][132];   // [k][col]

    const float* A = FIRST ? Ax : g_bufH;
    int tid = threadIdx.x;
    int tc = tid & 15;    // 16 col groups * 8 cols
    int tr = tid >> 4;    // 16 row groups * 8 rows
    int rowBase = blockIdx.x * 128;

    float acc[8][8];
    #pragma unroll
    for (int i = 0; i < 8; i++)
        #pragma unroll
        for (int j = 0; j < 8; j++) acc[i][j] = 0.f;

    for (int kk = 0; kk < 4; kk++) {
        #pragma unroll
        for (int p = 0; p < 4; p++) {
            int idx = p * 256 + tid;
            int r = idx >> 3;         // row 0..127
            int q = idx & 7;          // k-quad 0..7
            int gr = rowBase + r;
            float4 v = make_float4(0.f, 0.f, 0.f, 0.f);
            if (gr < N_NODES)
                v = *(const float4*)(A + (size_t)gr * 128 + kk * 32 + q * 4);
            if (ACT) {
                int c = kk * 32 + q * 4;
                v.x = fmaxf(fmaf(v.x, g_scale[c + 0], g_shift[c + 0]), 0.f);
                v.y = fmaxf(fmaf(v.y, g_scale[c + 1], g_shift[c + 1]), 0.f);
                v.z = fmaxf(fmaf(v.z, g_scale[c + 2], g_shift[c + 2]), 0.f);
                v.w = fmaxf(fmaf(v.w, g_scale[c + 3], g_shift[c + 3]), 0.f);
            }
            As[q * 4 + 0][r] = v.x;
            As[q * 4 + 1][r] = v.y;
            As[q * 4 + 2][r] = v.z;
            As[q * 4 + 3][r] = v.w;
        }
        #pragma unroll
        for (int p = 0; p < 4; p++) {
            int idx = p * 256 + tid;
            int r = idx >> 5;         // k 0..31
            int cq = idx & 31;        // col quad
            *(float4*)&Bs[r][cq * 4] =
                *(const float4*)(W + (size_t)(kk * 32 + r) * 128 + cq * 4);
        }
        __syncthreads();

        #pragma unroll
        for (int k = 0; k < 32; k++) {
            float4 a0 = *(const float4*)&As[k][tr * 8];
            float4 a1 = *(const float4*)&As[k][tr * 8 + 4];
            float4 b0 = *(const float4*)&Bs[k][tc * 8];
            float4 b1 = *(const float4*)&Bs[k][tc * 8 + 4];
            float av[8] = {a0.x, a0.y, a0.z, a0.w, a1.x, a1.y, a1.z, a1.w};
            float bv[8] = {b0.x, b0.y, b0.z, b0.w, b1.x, b1.y, b1.z, b1.w};
            #pragma unroll
            for (int i = 0; i < 8; i++)
                #pragma unroll
                for (int j = 0; j < 8; j++)
                    acc[i][j] = fmaf(av[i], bv[j], acc[i][j]);
        }
        __syncthreads();
    }

    #pragma unroll
    for (int i = 0; i < 8; i++) {
        int gr = rowBase + tr * 8 + i;
        if (gr < N_NODES) {
            float* dst = g_bufT + (size_t)gr * 128 + tc * 8;
            *(float4*)(dst + 0) = make_float4(acc[i][0], acc[i][1], acc[i][2], acc[i][3]);
            *(float4*)(dst + 4) = make_float4(acc[i][4], acc[i][5], acc[i][6], acc[i][7]);
        }
    }
}

// ---------------- BN accumulator zero ----------------
__global__ void k_zero_bn() {
    if (threadIdx.x < 256) g_bn[threadIdx.x] = 0.f;
}

// ---------------- aggregation: out = sum_e w_e * hT[src_e] + dinv^2 * hT[i] + bias
// fused: per-feature sum & sumsq for BatchNorm (reads/writes stay in L2)
__global__ __launch_bounds__(256)
void k_aggregate(const float* __restrict__ bias) {
    __shared__ float ssum[128];
    __shared__ float ssq[128];
    int lane = threadIdx.x & 31;
    int warp = threadIdx.x >> 5;   // 8 warps -> 8 nodes per group
    if (threadIdx.x < 128) { ssum[threadIdx.x] = 0.f; ssq[threadIdx.x] = 0.f; }

    float b0 = bias[lane * 4 + 0], b1 = bias[lane * 4 + 1];
    float b2 = bias[lane * 4 + 2], b3 = bias[lane * 4 + 3];

    float s0 = 0, s1 = 0, s2 = 0, s3 = 0;
    float q0 = 0, q1 = 0, q2 = 0, q3 = 0;

    for (int node = blockIdx.x * 8 + warp; node < N_NODES; node += gridDim.x * 8) {
        int beg = g_off[node];
        int end = g_off[node + 1];
        float di = g_dinv[node];
        float sw = di * di;
        float4 sv = *(const float4*)(g_bufT + (size_t)node * 128 + lane * 4);
        float a0 = sv.x * sw, a1 = sv.y * sw, a2 = sv.z * sw, a3 = sv.w * sw;
        for (int e = beg; e < end; e++) {
            int src = g_csr_src[e];
            float w = g_csr_w[e];
            float4 v = *(const float4*)(g_bufT + (size_t)src * 128 + lane * 4);
            a0 = fmaf(w, v.x, a0);
            a1 = fmaf(w, v.y, a1);
            a2 = fmaf(w, v.z, a2);
            a3 = fmaf(w, v.w, a3);
        }
        a0 += b0; a1 += b1; a2 += b2; a3 += b3;
        *(float4*)(g_bufH + (size_t)node * 128 + lane * 4) = make_float4(a0, a1, a2, a3);
        s0 += a0; q0 += a0 * a0;
        s1 += a1; q1 += a1 * a1;
        s2 += a2; q2 += a2 * a2;
        s3 += a3; q3 += a3 * a3;
    }
    __syncthreads();
    atomicAdd(&ssum[lane * 4 + 0], s0); atomicAdd(&ssq[lane * 4 + 0], q0);
    atomicAdd(&ssum[lane * 4 + 1], s1); atomicAdd(&ssq[lane * 4 + 1], q1);
    atomicAdd(&ssum[lane * 4 + 2], s2); atomicAdd(&ssq[lane * 4 + 2], q2);
    atomicAdd(&ssum[lane * 4 + 3], s3); atomicAdd(&ssq[lane * 4 + 3], q3);
    __syncthreads();
    if (threadIdx.x < 128) {
        atomicAdd(&g_bn[threadIdx.x], ssum[threadIdx.x]);
        atomicAdd(&g_bn[128 + threadIdx.x], ssq[threadIdx.x]);
    }
}

// ---------------- BN finalize: scale/shift for next consumer ----------------
__global__ void k_bn_finalize(const float* __restrict__ gamma, const float* __restrict__ beta) {
    int f = threadIdx.x;
    if (f < 128) {
        float invN = 1.0f / (float)N_NODES;
        float mu = g_bn[f] * invN;
        float var = g_bn[128 + f] * invN - mu * mu;
        float sc = gamma[f] * rsqrtf(var + EPS_BN);
        g_scale[f] = sc;
        g_shift[f] = beta[f] - mu * sc;
    }
}

// ---------------- pooling (applies layer-3 BN + relu; batch is sorted) ----------------
__global__ void k_zero_pool() {
    int i = blockIdx.x * blockDim.x + threadIdx.x;
    if (i < N_GRAPHS * DH) g_pool[i] = 0.f;
    if (i < N_GRAPHS) g_pcnt[i] = 0.f;
}

__global__ void k_pool(const void* __restrict__ batchv) {
    int t = threadIdx.x;   // feature 0..127
    int base = blockIdx.x * 128;
    int end = min(base + 128, N_NODES);
    float sc = g_scale[t], sh = g_shift[t];
    float acc = 0.f, cnt = 0.f;
    int cur = -1;
    for (int node = base; node < end; node++) {
        int g = load_idx(batchv, node, N_GRAPHS);
        if (g != cur) {
            if (cur >= 0) {
                atomicAdd(&g_pool[(size_t)cur * 128 + t], acc);
                if (t == 0) atomicAdd(&g_pcnt[cur], cnt);
            }
            cur = g; acc = 0.f; cnt = 0.f;
        }
        float v = fmaf(g_bufH[(size_t)node * 128 + t], sc, sh);
        acc += fmaxf(v, 0.f);
        cnt += 1.f;
    }
    if (cur >= 0) {
        atomicAdd(&g_pool[(size_t)cur * 128 + t], acc);
        if (t == 0) atomicAdd(&g_pcnt[cur], cnt);
    }
}

// ---------------- MLP head ----------------
__global__ void k_head(const float* __restrict__ W1, const float* __restrict__ b1,
                       const float* __restrict__ W2, const float* __restrict__ b2,
                       float* __restrict__ out) {
    __shared__ float z[128];
    __shared__ float red[4];
    int g = blockIdx.x;
    int t = threadIdx.x;
    float inv = 1.0f / fmaxf(g_pcnt[g], 1.0f);
    z[t] = g_pool[(size_t)g * 128 + t] * inv;
    __syncthreads();
    float hz = b1[t];
    #pragma unroll 16
    for (int k = 0; k < 128; k++) hz = fmaf(z[k], W1[(size_t)k * 128 + t], hz);
    hz = fmaxf(hz, 0.f);
    float p = hz * W2[t];
    #pragma unroll
    for (int o = 16; o > 0; o >>= 1) p += __shfl_down_sync(0xFFFFFFFFu, p, o);
    if ((t & 31) == 0) red[t >> 5] = p;
    __syncthreads();
    if (t == 0) out[g] = red[0] + red[1] + red[2] + red[3] + b2[0];
}

// ---------------- launcher ----------------
extern "C" void kernel_launch(void* const* d_in, const int* in_sizes, int n_in,
                              void* d_out, int out_size) {
    const float* x      = (const float*)d_in[0];
    const void*  ei     = d_in[1];                  // int32 or int64 (detected on device)
    const void*  batch  = d_in[2];
    const float* Ws     = (const float*)d_in[3];
    const float* bs     = (const float*)d_in[4];
    const float* gammas = (const float*)d_in[5];
    const float* betas  = (const float*)d_in[6];
    const float* W1     = (const float*)d_in[7];
    const float* b1     = (const float*)d_in[8];
    const float* W2     = (const float*)d_in[9];
    const float* b2     = (const float*)d_in[10];
    float* out = (float*)d_out;

    // dtype detection (safe either way: reads only the first 8 KB as int32)
    k_detect<<<1, 32>>>((const int*)ei);

    // CSR build (recomputed every launch: deterministic, no cached state)
    k_zero_deg<<<(N_NODES + 255) / 256, 256>>>();
    k_edge_deg<<<(N_EDGES + 255) / 256, 256>>>(ei);
    k_scan_local<<<NCHUNK, 512>>>();
    k_scan_chunks<<<1, 32>>>();
    k_scan_apply<<<NCHUNK, 512>>>();
    k_csr_fill<<<(N_EDGES + 255) / 256, 256>>>(ei);

    const int gemm_blocks = (N_NODES + 127) / 128;   // 782
    for (int l = 0; l < 3; l++) {
        if (l == 0)
            k_gemm<false, true><<<gemm_blocks, 256>>>(x, Ws + (size_t)l * DH * DH);
        else
            k_gemm<true, false><<<gemm_blocks, 256>>>(x, Ws + (size_t)l * DH * DH);
        k_zero_bn<<<1, 256>>>();
        k_aggregate<<<1480, 256>>>(bs + (size_t)l * DH);
        k_bn_finalize<<<1, 128>>>(gammas + (size_t)l * DH, betas + (size_t)l * DH);
    }

    k_zero_pool<<<(N_GRAPHS * DH + 255) / 256, 256>>>();
    k_pool<<<(N_NODES + 127) / 128, 128>>>(batch);
    k_head<<<N_GRAPHS, 128>>>(W1, b1, W2, b2, out);
}